// round 12
// baseline (speedup 1.0000x reference)
#include <cuda_runtime.h>
#include <math.h>

// Problem constants (fixed shapes from the reference)
#define B 128
#define C 512
#define HW 1024            // 32*32
#define E 16
#define KTOP 2
#define NOISE_STD_INV 16.0f   // 1 / (1/E) = E
#define TAU 1.0f
#define EPS 1e-8f

// Scratch (no allocations allowed in kernel_launch)
__device__ float g_pooled[B * C];   // 256 KB
__device__ float g_logits[B * E];
__device__ int   g_cnt[B];          // per-batch arrival tickets (self-reset)

// ---------------------------------------------------------------------------
// Kernel 1: pool (R1's proven 83.9%-DRAM shape: warp-per-row, v[8] batched,
// 256-thr blocks, NO launch_bounds reg forcing) + per-b ticket GEMM.
// 64 blocks cover one batch row b; the 64th to finish computes logits[b,:].
// That GEMM runs on early blocks while later pool waves still stream, so it
// is hidden under DRAM traffic except for the last row.
// ---------------------------------------------------------------------------
__global__ void pool_gemm_kernel(const float* __restrict__ x,
                                 const float* __restrict__ Wg) {
    __shared__ int s_flag;

    const int tid   = threadIdx.x;
    const int lane  = tid & 31;
    const int w     = tid >> 5;                       // 0..7
    const int gwarp = (blockIdx.x << 3) + w;          // global row (b,c)
    const int b     = blockIdx.x >> 6;                // 64 blocks per batch

    // ---- Pool: one warp per (b,c) row, 8 front-batched float4 loads.
    {
        const float4* row = reinterpret_cast<const float4*>(x + (size_t)gwarp * HW);
        float4 v[8];
#pragma unroll
        for (int j = 0; j < 8; ++j) v[j] = __ldg(&row[lane + 32 * j]);

        float s = 0.0f;
#pragma unroll
        for (int j = 0; j < 8; ++j) s += (v[j].x + v[j].y) + (v[j].z + v[j].w);

#pragma unroll
        for (int o = 16; o; o >>= 1) s += __shfl_xor_sync(0xffffffffu, s, o);
        if (lane == 0) g_pooled[gwarp] = s * (1.0f / (float)HW);
    }

    // ---- Ticket: last of the 64 blocks for batch b does that row's GEMM.
    __threadfence();
    __syncthreads();
    if (tid == 0) s_flag = (atomicAdd(&g_cnt[b], 1) == 63);
    __syncthreads();
    if (!s_flag) return;
    __threadfence();   // acquire: sibling blocks' g_pooled writes

    // ---- GEMM for row b: warp w -> experts w and w+8, lanes over C.
    {
        const float* prow = g_pooled + b * C;
        const float* w0   = Wg + w * C;
        const float* w1   = Wg + (w + 8) * C;
        float s0 = 0.0f, s1 = 0.0f;
#pragma unroll
        for (int j = 0; j < C / 32; ++j) {
            int c = lane + 32 * j;                    // coalesced L2
            float pv = __ldg(&prow[c]);
            s0 = fmaf(pv, __ldg(&w0[c]), s0);
            s1 = fmaf(pv, __ldg(&w1[c]), s1);
        }
#pragma unroll
        for (int o = 16; o; o >>= 1) {
            s0 += __shfl_xor_sync(0xffffffffu, s0, o);
            s1 += __shfl_xor_sync(0xffffffffu, s1, o);
        }
        if (lane == 0) {
            g_logits[b * E + w]     = s0;
            g_logits[b * E + w + 8] = s1;
        }
    }
    if (tid == 0) g_cnt[b] = 0;   // reset ticket for next graph replay
}

// ---------------------------------------------------------------------------
// Kernel 2: finalize only (1 block, 128 threads) — R1-validated code.
// Registers here never touch the streaming kernel.  Fixed-order reductions.
// ---------------------------------------------------------------------------
__global__ void finalize_kernel(const float* __restrict__ complexity,
                                const float* __restrict__ noise,
                                float* __restrict__ out) {
    __shared__ float sm_clean[B][E];   // 8 KB
    __shared__ float sm_p[B][E];       // 8 KB
    __shared__ float sh_imp[E];
    __shared__ float sh_pm[E];

    const int bb = threadIdx.x;
    if (bb < B) {
        float l[E], n[E];
#pragma unroll
        for (int e = 0; e < E; ++e) {
            l[e] = g_logits[bb * E + e];
            n[e] = l[e] + noise[bb * E + e];
        }
        // clean softmax
        {
            float mx = l[0];
#pragma unroll
            for (int e = 1; e < E; ++e) mx = fmaxf(mx, l[e]);
            float ssum = 0.0f, t2[E];
#pragma unroll
            for (int e = 0; e < E; ++e) { t2[e] = expf(l[e] - mx); ssum += t2[e]; }
            float inv = 1.0f / ssum;
#pragma unroll
            for (int e = 0; e < E; ++e) sm_clean[bb][e] = t2[e] * inv;
        }
        // noisy softmax
        float g[E];
        {
            float mx = n[0];
#pragma unroll
            for (int e = 1; e < E; ++e) mx = fmaxf(mx, n[e]);
            float ssum = 0.0f;
#pragma unroll
            for (int e = 0; e < E; ++e) { g[e] = expf(n[e] - mx); ssum += g[e]; }
            float inv = 1.0f / ssum;
#pragma unroll
            for (int e = 0; e < E; ++e) g[e] *= inv;
        }
        // top-2 (strict > => lowest index wins ties, matching jax.lax.top_k)
        int i1 = 0;
#pragma unroll
        for (int e = 1; e < E; ++e) if (g[e] > g[i1]) i1 = e;
        int i2 = (i1 == 0) ? 1 : 0;
#pragma unroll
        for (int e = 0; e < E; ++e) if (e != i1 && g[e] > g[i2]) i2 = e;
        float v1 = g[i1], v2 = g[i2];
        float thr = n[i2];   // 2nd-largest noisy logit

        // gates row + topk outputs
#pragma unroll
        for (int e = 0; e < E; ++e)
            out[bb * E + e] = (e == i1) ? v1 : ((e == i2) ? v2 : 0.0f);
        out[B * E + bb * KTOP + 0]            = (float)i1;
        out[B * E + bb * KTOP + 1]            = (float)i2;
        out[B * E + B * KTOP + bb * KTOP + 0] = v1;
        out[B * E + B * KTOP + bb * KTOP + 1] = v2;

        // p[e] = 1 - Phi((thr - l[e]) / sigma) = 0.5 * erfc(z / sqrt(2))
#pragma unroll
        for (int e = 0; e < E; ++e) {
            float z = (thr - l[e]) * NOISE_STD_INV;
            sm_p[bb][e] = 0.5f * erfcf(z * 0.70710678118654752f);
        }
    }
    __syncthreads();

    if (threadIdx.x < E) {
        int e = threadIdx.x;
        float si = 0.0f, sp = 0.0f;
        for (int r = 0; r < B; ++r) { si += sm_clean[r][e]; sp += sm_p[r][e]; }
        sh_imp[e] = si * (complexity[e] * TAU);
        sh_pm[e]  = sp * (1.0f / (float)B);
    }
    __syncthreads();

    if (threadIdx.x == 0) {
        float mi = 0.0f, mp = 0.0f;
#pragma unroll
        for (int e = 0; e < E; ++e) { mi += sh_imp[e]; mp += sh_pm[e]; }
        mi *= (1.0f / (float)E);
        mp *= (1.0f / (float)E);
        float vi = 0.0f, vp = 0.0f;
#pragma unroll
        for (int e = 0; e < E; ++e) {
            float di = sh_imp[e] - mi; vi += di * di;
            float dp = sh_pm[e]  - mp; vp += dp * dp;
        }
        vi *= (1.0f / (float)(E - 1));   // ddof=1
        vp *= (1.0f / (float)(E - 1));
        float cvi = sqrtf(vi) / (mi + EPS);
        float cvp = sqrtf(vp) / (mp + EPS);
        out[B * E + 2 * B * KTOP] = 0.5f * (cvi * cvi) + 0.5f * (cvp * cvp);
    }
}

// ---------------------------------------------------------------------------
extern "C" void kernel_launch(void* const* d_in, const int* in_sizes, int n_in,
                              void* d_out, int out_size) {
    const float* x          = (const float*)d_in[0];
    const float* W_gate     = (const float*)d_in[1];
    const float* complexity = (const float*)d_in[2];
    const float* noise      = (const float*)d_in[3];
    float* out = (float*)d_out;

    // 8192 blocks x 256 threads: warp-per-row pool, 64 blocks per batch row.
    pool_gemm_kernel<<<B * C / 8, 256>>>(x, W_gate);
    finalize_kernel<<<1, 128>>>(complexity, noise, out);
}

// round 14
// speedup vs baseline: 1.2101x; 1.2101x over previous
#include <cuda_runtime.h>
#include <math.h>

// Problem constants (fixed shapes from the reference)
#define B 128
#define C 512
#define HW 1024            // 32*32
#define E 16
#define KTOP 2
#define NOISE_STD_INV 16.0f   // 1 / (1/E) = E
#define TAU 1.0f
#define EPS 1e-8f

// Scratch (no allocations allowed in kernel_launch)
__device__ float g_pooled[B * C];   // 256 KB
__device__ float g_logits[B * E];

// ---------------------------------------------------------------------------
// Kernel 1: adaptive avg pool.  EXACT R1 kernel (measured 83.9% DRAM, 41.1us).
// ---------------------------------------------------------------------------
__global__ void __launch_bounds__(256) pool_kernel(const float* __restrict__ x) {
    int gwarp = (blockIdx.x * blockDim.x + threadIdx.x) >> 5;
    int lane  = threadIdx.x & 31;

    const float4* row = reinterpret_cast<const float4*>(x + (size_t)gwarp * HW);
    float4 v[8];
#pragma unroll
    for (int j = 0; j < 8; ++j) v[j] = __ldg(&row[lane + 32 * j]);

    float s = 0.0f;
#pragma unroll
    for (int j = 0; j < 8; ++j) s += (v[j].x + v[j].y) + (v[j].z + v[j].w);

#pragma unroll
    for (int o = 16; o; o >>= 1) s += __shfl_xor_sync(0xffffffffu, s, o);
    if (lane == 0) g_pooled[gwarp] = s * (1.0f / (float)HW);
}

// ---------------------------------------------------------------------------
// Kernel 2: logits = pooled @ W_gate^T.  EXACT R1 kernel (proven).
// One block per b, pooled row staged in smem, one warp per expert.
// ---------------------------------------------------------------------------
__global__ void gate_gemm_kernel(const float* __restrict__ Wg) {
    __shared__ float sp[C];
    int b = blockIdx.x;
    sp[threadIdx.x] = g_pooled[b * C + threadIdx.x];
    __syncthreads();

    int e    = threadIdx.x >> 5;   // 0..15
    int lane = threadIdx.x & 31;
    const float* wrow = Wg + e * C;
    float s = 0.0f;
#pragma unroll
    for (int j = 0; j < C / 32; ++j)
        s = fmaf(sp[lane + 32 * j], __ldg(&wrow[lane + 32 * j]), s);
#pragma unroll
    for (int o = 16; o; o >>= 1) s += __shfl_xor_sync(0xffffffffu, s, o);
    if (lane == 0) g_logits[b * E + e] = s;
}

// ---------------------------------------------------------------------------
// Kernel 3: finalize, WIDE layout: 1024 threads, thread = (row, expert).
// 16-lane segmented shfl butterflies for softmax + top-2; per-thread math is
// only 2x(2 exp + 1 erfc).  Fixed-order two-stage tree sums -> deterministic.
// ---------------------------------------------------------------------------
__global__ void __launch_bounds__(1024) finalize_kernel(
        const float* __restrict__ complexity,
        const float* __restrict__ noise,
        float* __restrict__ out) {
    __shared__ float sm_clean[B][E];   // 8 KB
    __shared__ float sm_p[B][E];       // 8 KB
    __shared__ float part_imp[16][E];  // 1 KB
    __shared__ float part_pm[16][E];   // 1 KB
    __shared__ float sh_imp[E];
    __shared__ float sh_pm[E];

    const unsigned FULL = 0xffffffffu;
    const int t    = threadIdx.x;
    const int lane = t & 31;
    const int e    = t & 15;       // expert
    const int seg  = t >> 4;       // 0..63 row-segment
    const int sbase = lane & 16;   // 16-lane segment base within warp

#pragma unroll
    for (int iter = 0; iter < 2; ++iter) {
        const int b = seg + 64 * iter;
        float l  = g_logits[b * E + e];
        float nz = l + noise[b * E + e];

        // clean softmax prob for (b,e) via 16-lane butterflies
        float mx = l;
#pragma unroll
        for (int o = 8; o; o >>= 1) mx = fmaxf(mx, __shfl_xor_sync(FULL, mx, o));
        float ex = __expf(l - mx);
        float es = ex;
#pragma unroll
        for (int o = 8; o; o >>= 1) es += __shfl_xor_sync(FULL, es, o);
        sm_clean[b][e] = ex / es;

        // noisy softmax prob
        float mn = nz;
#pragma unroll
        for (int o = 8; o; o >>= 1) mn = fmaxf(mn, __shfl_xor_sync(FULL, mn, o));
        float eg = __expf(nz - mn);
        float gs = eg;
#pragma unroll
        for (int o = 8; o; o >>= 1) gs += __shfl_xor_sync(FULL, gs, o);
        float g = eg / gs;

        // top-1 of nz (ties -> lowest index, matching jax.lax.top_k)
        float v = nz; int idx = e;
#pragma unroll
        for (int o = 8; o; o >>= 1) {
            float vo = __shfl_xor_sync(FULL, v, o);
            int   io = __shfl_xor_sync(FULL, idx, o);
            if (vo > v || (vo == v && io < idx)) { v = vo; idx = io; }
        }
        const int i1 = idx;

        // top-2: mask out i1, reduce again
        float vm = (e == i1) ? -3.4e38f : nz;
        int  idx2 = e;
#pragma unroll
        for (int o = 8; o; o >>= 1) {
            float vo = __shfl_xor_sync(FULL, vm, o);
            int   io = __shfl_xor_sync(FULL, idx2, o);
            if (vo > vm || (vo == vm && io < idx2)) { vm = vo; idx2 = io; }
        }
        const int i2 = idx2;

        float v1  = __shfl_sync(FULL, g,  sbase | i1);
        float v2  = __shfl_sync(FULL, g,  sbase | i2);
        float thr = __shfl_sync(FULL, nz, sbase | i2);

        // gates row (every (b,e) written by its own thread)
        out[b * E + e] = (e == i1) ? v1 : ((e == i2) ? v2 : 0.0f);
        if (e == 0) {
            out[B * E + b * KTOP + 0]            = (float)i1;
            out[B * E + b * KTOP + 1]            = (float)i2;
            out[B * E + B * KTOP + b * KTOP + 0] = v1;
            out[B * E + B * KTOP + b * KTOP + 1] = v2;
        }

        // load-balance p: 1 - Phi((thr - l)/sigma) = 0.5*erfc(z/sqrt2)
        float z = (thr - l) * NOISE_STD_INV;
        sm_p[b][e] = 0.5f * erfcf(z * 0.70710678118654752f);
    }
    __syncthreads();

    // column sums over B: stage 1 = 16 chunks of 8 rows (256 threads)
    if (t < 256) {
        int ee = t & 15, chunk = t >> 4;
        float si = 0.0f, sp = 0.0f;
#pragma unroll
        for (int r = chunk * 8; r < chunk * 8 + 8; ++r) {
            si += sm_clean[r][ee];
            sp += sm_p[r][ee];
        }
        part_imp[chunk][ee] = si;
        part_pm[chunk][ee]  = sp;
    }
    __syncthreads();
    // stage 2: fixed-order combine of 16 partials
    if (t < E) {
        float si = 0.0f, sp = 0.0f;
#pragma unroll
        for (int c = 0; c < 16; ++c) { si += part_imp[c][t]; sp += part_pm[c][t]; }
        sh_imp[t] = si * (complexity[t] * TAU);
        sh_pm[t]  = sp * (1.0f / (float)B);
    }
    __syncthreads();

    if (t == 0) {
        float mi = 0.0f, mp = 0.0f;
#pragma unroll
        for (int e2 = 0; e2 < E; ++e2) { mi += sh_imp[e2]; mp += sh_pm[e2]; }
        mi *= (1.0f / (float)E);
        mp *= (1.0f / (float)E);
        float vi = 0.0f, vp = 0.0f;
#pragma unroll
        for (int e2 = 0; e2 < E; ++e2) {
            float di = sh_imp[e2] - mi; vi += di * di;
            float dp = sh_pm[e2]  - mp; vp += dp * dp;
        }
        vi *= (1.0f / (float)(E - 1));   // ddof=1
        vp *= (1.0f / (float)(E - 1));
        float cvi = sqrtf(vi) / (mi + EPS);
        float cvp = sqrtf(vp) / (mp + EPS);
        out[B * E + 2 * B * KTOP] = 0.5f * (cvi * cvi) + 0.5f * (cvp * cvp);
    }
}

// ---------------------------------------------------------------------------
extern "C" void kernel_launch(void* const* d_in, const int* in_sizes, int n_in,
                              void* d_out, int out_size) {
    const float* x          = (const float*)d_in[0];
    const float* W_gate     = (const float*)d_in[1];
    const float* complexity = (const float*)d_in[2];
    const float* noise      = (const float*)d_in[3];
    float* out = (float*)d_out;

    pool_kernel<<<B * C / 8, 256>>>(x);            // proven 83.9% DRAM shape
    gate_gemm_kernel<<<B, C>>>(W_gate);            // proven R1 tail
    finalize_kernel<<<1, 1024>>>(complexity, noise, out);
}

// round 15
// speedup vs baseline: 1.2553x; 1.0374x over previous
#include <cuda_runtime.h>
#include <math.h>

// Problem constants (fixed shapes from the reference)
#define B 128
#define C 512
#define HW 1024            // 32*32
#define E 16
#define KTOP 2
#define NOISE_STD_INV 16.0f   // 1 / (1/E) = E
#define TAU 1.0f
#define EPS 1e-8f

// Scratch (no allocations allowed in kernel_launch)
__device__ float g_pooled[B * C];   // 256 KB
__device__ float g_logits[B * E];

// ---------------------------------------------------------------------------
// Kernel 1: adaptive avg pool.  EXACT R1/R14 kernel (83.9% DRAM, 41.0us),
// plus an early PDL trigger so dependent kernels launch under the stream.
// ---------------------------------------------------------------------------
__global__ void __launch_bounds__(256) pool_kernel(const float* __restrict__ x) {
    int gwarp = (blockIdx.x * blockDim.x + threadIdx.x) >> 5;
    int lane  = threadIdx.x & 31;

    const float4* row = reinterpret_cast<const float4*>(x + (size_t)gwarp * HW);
    float4 v[8];
#pragma unroll
    for (int j = 0; j < 8; ++j) v[j] = __ldg(&row[lane + 32 * j]);

    float s = 0.0f;
#pragma unroll
    for (int j = 0; j < 8; ++j) s += (v[j].x + v[j].y) + (v[j].z + v[j].w);

#pragma unroll
    for (int o = 16; o; o >>= 1) s += __shfl_xor_sync(0xffffffffu, s, o);
    if (lane == 0) g_pooled[gwarp] = s * (1.0f / (float)HW);

    cudaTriggerProgrammaticLaunchCompletion();
}

// ---------------------------------------------------------------------------
// Kernel 2: logits = pooled @ W_gate^T.  PDL secondary: preload W into regs
// (independent input), THEN wait for pool, then consume g_pooled.
// One block per b (512 thr), warp per expert.
// ---------------------------------------------------------------------------
__global__ void __launch_bounds__(512) gate_gemm_kernel(const float* __restrict__ Wg) {
    __shared__ float sp[C];
    const int tid  = threadIdx.x;
    const int e    = tid >> 5;     // 0..15
    const int lane = tid & 31;
    const int b    = blockIdx.x;

    // Prelude (overlaps pool): W row values for this lane -> registers.
    float wv[C / 32];
    const float* wrow = Wg + e * C;
#pragma unroll
    for (int j = 0; j < C / 32; ++j) wv[j] = __ldg(&wrow[lane + 32 * j]);

    cudaGridDependencySynchronize();   // pool results now visible

    sp[tid] = g_pooled[b * C + tid];
    __syncthreads();

    float s = 0.0f;
#pragma unroll
    for (int j = 0; j < C / 32; ++j)
        s = fmaf(sp[lane + 32 * j], wv[j], s);
#pragma unroll
    for (int o = 16; o; o >>= 1) s += __shfl_xor_sync(0xffffffffu, s, o);
    if (lane == 0) g_logits[b * E + e] = s;

    cudaTriggerProgrammaticLaunchCompletion();
}

// ---------------------------------------------------------------------------
// Kernel 3: finalize, wide layout (R14-validated): 1024 threads,
// thread = (row-segment, expert); 16-lane shfl butterflies; fixed-order sums.
// PDL secondary: preload noise/complexity before waiting on the GEMM.
// ---------------------------------------------------------------------------
__global__ void __launch_bounds__(1024) finalize_kernel(
        const float* __restrict__ complexity,
        const float* __restrict__ noise,
        float* __restrict__ out) {
    __shared__ float sm_clean[B][E];   // 8 KB
    __shared__ float sm_p[B][E];       // 8 KB
    __shared__ float part_imp[16][E];  // 1 KB
    __shared__ float part_pm[16][E];   // 1 KB
    __shared__ float sh_imp[E];
    __shared__ float sh_pm[E];

    const unsigned FULL = 0xffffffffu;
    const int t    = threadIdx.x;
    const int lane = t & 31;
    const int e    = t & 15;       // expert
    const int seg  = t >> 4;       // 0..63 row-segment
    const int sbase = lane & 16;   // 16-lane segment base within warp

    // Prelude (overlaps pool/GEMM): independent inputs -> registers.
    float nz_pre[2];
    nz_pre[0] = __ldg(&noise[(seg)      * E + e]);
    nz_pre[1] = __ldg(&noise[(seg + 64) * E + e]);
    float comp_e = __ldg(&complexity[e]);

    cudaGridDependencySynchronize();   // logits now visible

#pragma unroll
    for (int iter = 0; iter < 2; ++iter) {
        const int b = seg + 64 * iter;
        float l  = g_logits[b * E + e];
        float nz = l + nz_pre[iter];

        // clean softmax prob via 16-lane butterflies
        float mx = l;
#pragma unroll
        for (int o = 8; o; o >>= 1) mx = fmaxf(mx, __shfl_xor_sync(FULL, mx, o));
        float ex = __expf(l - mx);
        float es = ex;
#pragma unroll
        for (int o = 8; o; o >>= 1) es += __shfl_xor_sync(FULL, es, o);
        sm_clean[b][e] = ex / es;

        // noisy softmax prob
        float mn = nz;
#pragma unroll
        for (int o = 8; o; o >>= 1) mn = fmaxf(mn, __shfl_xor_sync(FULL, mn, o));
        float eg = __expf(nz - mn);
        float gs = eg;
#pragma unroll
        for (int o = 8; o; o >>= 1) gs += __shfl_xor_sync(FULL, gs, o);
        float g = eg / gs;

        // top-1 of nz (ties -> lowest index, matching jax.lax.top_k)
        float v = nz; int idx = e;
#pragma unroll
        for (int o = 8; o; o >>= 1) {
            float vo = __shfl_xor_sync(FULL, v, o);
            int   io = __shfl_xor_sync(FULL, idx, o);
            if (vo > v || (vo == v && io < idx)) { v = vo; idx = io; }
        }
        const int i1 = idx;

        // top-2: mask out i1, reduce again
        float vm = (e == i1) ? -3.4e38f : nz;
        int  idx2 = e;
#pragma unroll
        for (int o = 8; o; o >>= 1) {
            float vo = __shfl_xor_sync(FULL, vm, o);
            int   io = __shfl_xor_sync(FULL, idx2, o);
            if (vo > vm || (vo == vm && io < idx2)) { vm = vo; idx2 = io; }
        }
        const int i2 = idx2;

        float v1  = __shfl_sync(FULL, g,  sbase | i1);
        float v2  = __shfl_sync(FULL, g,  sbase | i2);
        float thr = __shfl_sync(FULL, nz, sbase | i2);

        // gates row (every (b,e) written by its own thread)
        out[b * E + e] = (e == i1) ? v1 : ((e == i2) ? v2 : 0.0f);
        if (e == 0) {
            out[B * E + b * KTOP + 0]            = (float)i1;
            out[B * E + b * KTOP + 1]            = (float)i2;
            out[B * E + B * KTOP + b * KTOP + 0] = v1;
            out[B * E + B * KTOP + b * KTOP + 1] = v2;
        }

        // load-balance p: 1 - Phi((thr - l)/sigma) = 0.5*erfc(z/sqrt2)
        float z = (thr - l) * NOISE_STD_INV;
        sm_p[b][e] = 0.5f * erfcf(z * 0.70710678118654752f);
    }
    __syncthreads();

    // column sums over B: stage 1 = 16 chunks of 8 rows (256 threads)
    if (t < 256) {
        int ee = t & 15, chunk = t >> 4;
        float si = 0.0f, sp = 0.0f;
#pragma unroll
        for (int r = chunk * 8; r < chunk * 8 + 8; ++r) {
            si += sm_clean[r][ee];
            sp += sm_p[r][ee];
        }
        part_imp[chunk][ee] = si;
        part_pm[chunk][ee]  = sp;
    }
    __syncthreads();
    // stage 2: fixed-order combine of 16 partials
    if (t < E) {
        float si = 0.0f, sp = 0.0f;
#pragma unroll
        for (int c = 0; c < 16; ++c) { si += part_imp[c][t]; sp += part_pm[c][t]; }
        sh_imp[t] = si * (comp_e * TAU);     // comp_e == complexity[t] since t==e here
        sh_pm[t]  = sp * (1.0f / (float)B);
    }
    __syncthreads();

    if (t == 0) {
        float mi = 0.0f, mp = 0.0f;
#pragma unroll
        for (int e2 = 0; e2 < E; ++e2) { mi += sh_imp[e2]; mp += sh_pm[e2]; }
        mi *= (1.0f / (float)E);
        mp *= (1.0f / (float)E);
        float vi = 0.0f, vp = 0.0f;
#pragma unroll
        for (int e2 = 0; e2 < E; ++e2) {
            float di = sh_imp[e2] - mi; vi += di * di;
            float dp = sh_pm[e2]  - mp; vp += dp * dp;
        }
        vi *= (1.0f / (float)(E - 1));   // ddof=1
        vp *= (1.0f / (float)(E - 1));
        float cvi = sqrtf(vi) / (mi + EPS);
        float cvp = sqrtf(vp) / (mp + EPS);
        out[B * E + 2 * B * KTOP] = 0.5f * (cvi * cvi) + 0.5f * (cvp * cvp);
    }
}

// ---------------------------------------------------------------------------
extern "C" void kernel_launch(void* const* d_in, const int* in_sizes, int n_in,
                              void* d_out, int out_size) {
    const float* x          = (const float*)d_in[0];
    const float* W_gate     = (const float*)d_in[1];
    const float* complexity = (const float*)d_in[2];
    const float* noise      = (const float*)d_in[3];
    float* out = (float*)d_out;

    pool_kernel<<<B * C / 8, 256>>>(x);    // proven 83.9% DRAM shape

    // PDL launches: overlap tail launch latency + input prefetch with pool.
    cudaLaunchAttribute attr[1];
    attr[0].id = cudaLaunchAttributeProgrammaticStreamSerialization;
    attr[0].val.programmaticStreamSerializationAllowed = 1;

    cudaLaunchConfig_t cfg = {};
    cfg.attrs    = attr;
    cfg.numAttrs = 1;
    cfg.stream   = 0;

    cfg.gridDim  = dim3(B);
    cfg.blockDim = dim3(C);
    cudaLaunchKernelEx(&cfg, gate_gemm_kernel, W_gate);

    cfg.gridDim  = dim3(1);
    cfg.blockDim = dim3(1024);
    cudaLaunchKernelEx(&cfg, finalize_kernel, complexity, noise, out);
}